// round 16
// baseline (speedup 1.0000x reference)
#include <cuda_runtime.h>
#include <cuda_fp16.h>
#include <math.h>
#include <stdint.h>

// ---------------- problem constants ----------------
#define THREADS   320
#define MROWS     64          // batch rows per CTA (3 CTAs/SM)
#define D1        32
#define DFF       256
#define D2        32
#define NBINS     16
#define DOUT      1568        // 49*32
#define NCH       32          // one chunk per output j
#define NTILES    7           // n8 tiles per chunk (49 -> 56 padded)
#define HSTR      36          // h1T padded stride (floats)
#define PRMSTR    51          // prm stride (floats), odd -> conflict-free spline reads
#define TAILF     3.0f
#define MINVF     0.001f
#define EPSF      1e-6f

// ---------------- smem byte offsets (total 74496 per CTA -> 3 CTAs/SM) -------
#define SM_A_HI   0                         // 64x256 f16, 512B/row, XOR16 swizzle (32768 B)
#define SM_B      32768                     // B tile 7*16*32 uint2 = 28672 B
#define SM_PRM    61440                     // 64x51 f32 = 13056 B  (ends 74496)
// phase-only overlays (B+prm region unused during phases):
#define SM_H1     32768                     // 256x36 f32 = 36864 B (ends 69632)
#define SM_X1     69632                     // 32x32 f32 = 4096 B   (ends 73728)
#define SMEM_TOTAL 74496

#define B_TILE_U2 (NTILES * 16 * 32)        // 3584 uint2 per chunk
#define B_TILE_U4 (B_TILE_U2 / 2)           // 1792 uint4

typedef unsigned long long u64;

// prepped W3 hi-fragments: [c][nt][kk][lane] -> uint2{hi_b0, hi_b1}
__device__ __align__(16) uint2 g_W3B[NCH * NTILES * 16 * 32];   // 917504 B

// ---------------- helpers ----------------
__device__ __forceinline__ u64 pack2(float lo, float hi) {
    u64 r; asm("mov.b64 %0, {%1, %2};" : "=l"(r) : "f"(lo), "f"(hi)); return r;
}
__device__ __forceinline__ void unpack2(u64 v, float& lo, float& hi) {
    asm("mov.b64 {%0, %1}, %2;" : "=f"(lo), "=f"(hi) : "l"(v));
}
__device__ __forceinline__ void fma2(u64& d, u64 a, u64 b) {
    asm("fma.rn.f32x2 %0, %1, %2, %0;" : "+l"(d) : "l"(a), "l"(b));
}
__device__ __forceinline__ float softplusf(float x) {
    return fmaxf(x, 0.0f) + log1pf(__expf(-fabsf(x)));
}
__device__ __forceinline__ uint32_t smem_u32(const void* p) {
    uint32_t a;
    asm("{ .reg .u64 t; cvta.to.shared.u64 t, %1; cvt.u32.u64 %0, t; }" : "=r"(a) : "l"(p));
    return a;
}
#define CP_ASYNC16(dst, src) \
    asm volatile("cp.async.cg.shared.global [%0], [%1], 16;" :: "r"(dst), "l"(src))
#define CP_COMMIT() asm volatile("cp.async.commit_group;" ::: "memory")
#define CP_WAIT0()  asm volatile("cp.async.wait_group 0;" ::: "memory")

// ---------------- tensor-core primitives (baseline ISA, sm_80+) ----------------
__device__ __forceinline__ void ldsm_x4(uint32_t addr, uint32_t r[4]) {
    asm volatile("ldmatrix.sync.aligned.m8n8.x4.shared.b16 {%0,%1,%2,%3}, [%4];"
                 : "=r"(r[0]), "=r"(r[1]), "=r"(r[2]), "=r"(r[3]) : "r"(addr));
}
__device__ __forceinline__ void mma16816(float d[4], const uint32_t a[4],
                                         uint32_t b0, uint32_t b1) {
    asm volatile("mma.sync.aligned.m16n8k16.row.col.f32.f16.f16.f32 "
                 "{%0,%1,%2,%3}, {%4,%5,%6,%7}, {%8,%9}, {%0,%1,%2,%3};"
                 : "+f"(d[0]), "+f"(d[1]), "+f"(d[2]), "+f"(d[3])
                 : "r"(a[0]), "r"(a[1]), "r"(a[2]), "r"(a[3]), "r"(b0), "r"(b1));
}
__device__ __forceinline__ uint32_t hpack(__half a, __half b) {
    uint32_t r;
    asm("mov.b32 %0, {%1, %2};" : "=r"(r) : "h"(__half_as_ushort(a)), "h"(__half_as_ushort(b)));
    return r;
}

// =====================================================================
// prep kernel: W3 [256 x 1568] -> per-lane hi B fragments, 7 tiles/chunk
// =====================================================================
__global__ void prep_w3_kernel(const float* __restrict__ W3) {
    int id = blockIdx.x * blockDim.x + threadIdx.x;
    if (id >= NCH * NTILES * 16 * 32) return;
    const int lane = id & 31;
    const int kk   = (id >> 5) & 15;
    const int rest = id >> 9;
    const int nt   = rest % NTILES;
    const int c    = rest / NTILES;
    const int g = lane >> 2, tg = lane & 3;
    const int n = nt * 8 + g;                 // 0..55
    float w00 = 0.f, w01 = 0.f, w10 = 0.f, w11 = 0.f;
    if (n < 49) {
        const size_t pi = (size_t)c * 49 + n;
        const int k0 = kk * 16 + 2 * tg;
        w00 = W3[(size_t)(k0    ) * DOUT + pi];
        w01 = W3[(size_t)(k0 + 1) * DOUT + pi];
        w10 = W3[(size_t)(k0 + 8) * DOUT + pi];
        w11 = W3[(size_t)(k0 + 9) * DOUT + pi];
    }
    uint2 v;
    v.x = hpack(__float2half_rn(w00), __float2half_rn(w01));
    v.y = hpack(__float2half_rn(w10), __float2half_rn(w11));
    g_W3B[((c * NTILES + nt) * 16 + kk) * 32 + lane] = v;
}

// =====================================================================
// main fused kernel: 3 CTAs/SM, single f16 product (Ah*Bh)
//   warps 0-7: MMA (mt4 x nh2, M16 x N32/24); warps 8-9: spline(c-1)
// =====================================================================
__global__ __launch_bounds__(THREADS, 3)
void rq_fused_kernel(const float* __restrict__ x1,
                     const float* __restrict__ x2,
                     const float* __restrict__ W1,
                     const float* __restrict__ b1,
                     const float* __restrict__ W2,
                     const float* __restrict__ b2,
                     const float* __restrict__ b3,
                     float* __restrict__ zout,
                     float* __restrict__ ldout)
{
    extern __shared__ char smem[];
    const uint32_t sbase = smem_u32(smem);
    float* x1s = (float*)(smem + SM_X1);
    float* h1T = (float*)(smem + SM_H1);
    float* prm = (float*)(smem + SM_PRM);
    const uint2* Bsm = (const uint2*)(smem + SM_B);

    const int t    = threadIdx.x;
    const int wid  = t >> 5;
    const int lane = t & 31;
    const int row0 = blockIdx.x * MROWS;

    // ---------------- phases 1+2 (SIMT fp32x2, threads 0-255): 2 sub-blocks of 32 rows
    for (int sub = 0; sub < 2; sub++) {
        if (t < 256)
            for (int i = t; i < 32 * D1; i += 256)
                x1s[i] = x1[(size_t)(row0 + sub * 32) * D1 + i];
        __syncthreads();

        if (t < 256) {
            const int col = t;
            // phase 1: h1 = relu(x1 @ W1 + b1), 32 rows
            float w1r[D1];
            #pragma unroll
            for (int k = 0; k < D1; k++) w1r[k] = W1[k * DFF + col];
            const float bb = b1[col];
            #pragma unroll
            for (int rr = 0; rr < 32; rr++) {
                float acc = bb;
                #pragma unroll
                for (int k = 0; k < D1; k++)
                    acc = fmaf(x1s[rr * D1 + k], w1r[k], acc);
                h1T[col * HSTR + rr] = fmaxf(acc, 0.0f);
            }
        }
        __syncthreads();

        if (t < 256) {
            const int col = t;
            // phase 2: h2 = relu(h1 @ W2 + b2) -> A_hi f16 (XOR16-swizzled)
            u64 acc2[16];
            const float bb = b2[col];
            #pragma unroll
            for (int q = 0; q < 16; q++) acc2[q] = pack2(bb, bb);
            #pragma unroll 4
            for (int k = 0; k < DFF; k++) {
                const float w = __ldg(W2 + k * DFF + col);
                const u64 w2 = pack2(w, w);
                const ulonglong2* h4 = reinterpret_cast<const ulonglong2*>(h1T + k * HSTR);
                #pragma unroll
                for (int q = 0; q < 8; q++) {
                    ulonglong2 a = h4[q];
                    fma2(acc2[2*q + 0], a.x, w2);
                    fma2(acc2[2*q + 1], a.y, w2);
                }
            }
            #pragma unroll
            for (int q = 0; q < 16; q++) {
                float lo, hi;
                unpack2(acc2[q], lo, hi);
                #pragma unroll
                for (int e = 0; e < 2; e++) {
                    const float v = fmaxf(e ? hi : lo, 0.0f);
                    const int r = sub * 32 + 2 * q + e;
                    const uint32_t ao = (uint32_t)(r * 512 + col * 2) ^ ((uint32_t)(r & 7) << 4);
                    *(__half*)(smem + SM_A_HI + ao) = __float2half_rn(v);
                }
            }
        }
        __syncthreads();
    }

    // preload B chunk 0 (28672 B = 1792 uint4)
    {
        const uint4* src = (const uint4*)g_W3B;
        for (int i = t; i < B_TILE_U4; i += THREADS)
            CP_ASYNC16(sbase + SM_B + i * 16, (const void*)(src + i));
        CP_COMMIT(); CP_WAIT0();
    }
    __syncthreads();

    // =====================================================================
    // chunk pipeline (single B buffer, refilled between syncs)
    // =====================================================================
    float ldsum = 0.0f;

    const int mt = wid & 3;        // 16-row M-tile (0-3)
    const int nh = wid >> 2;       // 0: tiles 0-3, 1: tiles 4-6
    const int tbase = nh * 4;
    const uint32_t arow  = (uint32_t)(mt * 16 + (lane & 15));
    const uint32_t abase = arow * 512 + ((lane >> 4) << 4);
    const uint32_t aswz  = (arow & 7) << 4;

    // spline-side x2 prefetch (one chunk ahead)
    float x_next = 0.0f;
    if (wid >= 8) {
        const int rr = t - 256;                              // 0..63
        x_next = __ldg(x2 + (size_t)(row0 + rr) * D2 + 0);   // j=0
    }

    #pragma unroll 1
    for (int c = 0; c < NCH; c++) {
        float d[16];
        if (wid < 8) {
            // ------------------ MMA mainloop (hi*hi only), double-buffered frags -----
            #pragma unroll
            for (int i = 0; i < 16; i++) d[i] = 0.0f;

            uint32_t ah[2][4];
            uint2 bb[2][4];
            {   // preload kk = 0
                const uint32_t o = abase ^ aswz;
                ldsm_x4(sbase + SM_A_HI + o, ah[0]);
                #pragma unroll
                for (int nt4 = 0; nt4 < 4; nt4++)
                    if (tbase + nt4 < NTILES)
                        bb[0][nt4] = Bsm[((tbase + nt4) * 16 + 0) * 32 + lane];
            }
            #pragma unroll
            for (int kk = 0; kk < 16; kk++) {
                const int cur = kk & 1, nxt = cur ^ 1;
                if (kk < 15) {
                    const uint32_t o = (abase + (kk + 1) * 32) ^ aswz;
                    ldsm_x4(sbase + SM_A_HI + o, ah[nxt]);
                    #pragma unroll
                    for (int nt4 = 0; nt4 < 4; nt4++)
                        if (tbase + nt4 < NTILES)
                            bb[nxt][nt4] = Bsm[((tbase + nt4) * 16 + (kk + 1)) * 32 + lane];
                }
                #pragma unroll
                for (int nt4 = 0; nt4 < 4; nt4++)
                    if (tbase + nt4 < NTILES)
                        mma16816(d + nt4 * 4, ah[cur], bb[cur][nt4].x, bb[cur][nt4].y);
            }
        } else if (c > 0) {
            // ------------------ spline warps: chunk c-1, row rr = t-256 --------------
            const int rr   = t - 256;          // 0..63
            const int grow = row0 + rr;
            const int j    = c - 1;
            const float* pp = prm + rr * PRMSTR;

            const float x = x_next;
            if (c < NCH) x_next = __ldg(x2 + (size_t)grow * D2 + c);
            const bool inside = (x >= -TAILF) && (x <= TAILF);
            const float xc = fminf(fmaxf(x, -TAILF), TAILF);

            float mw = -1e30f, mh = -1e30f;
            #pragma unroll
            for (int i = 0; i < NBINS; i++) {
                mw = fmaxf(mw, pp[i]);
                mh = fmaxf(mh, pp[NBINS + i]);
            }
            float ew[NBINS], eh[NBINS];
            float sw = 0.0f, sh = 0.0f;
            #pragma unroll
            for (int i = 0; i < NBINS; i++) {
                ew[i] = __expf(pp[i] - mw);          sw += ew[i];
                eh[i] = __expf(pp[NBINS + i] - mh);  sh += eh[i];
            }
            const float cscale = 1.0f - NBINS * MINVF;
            const float rw = cscale / sw;
            const float rhh = cscale / sh;

            float S = 0.0f;
            float cw_lo = -TAILF, cw_lo_prev = -TAILF, cw_hi = TAILF;
            int idx = 0;
            bool failed = false;
            #pragma unroll
            for (int m = 1; m <= NBINS; m++) {
                S += MINVF + rw * ew[m - 1];
                const float cwm = fmaf(2.0f * TAILF, S, -TAILF);
                const float ref = (m == NBINS) ? (cwm + EPSF) : cwm;
                if (ref <= xc) { idx = m; cw_lo_prev = cw_lo; cw_lo = cwm; }
                else if (!failed) { failed = true; cw_hi = cwm; }
            }
            if (!failed) { idx = NBINS - 1; cw_hi = cw_lo; cw_lo = cw_lo_prev; }

            float Sh = 0.0f;
            float ch_lo = -TAILF, ch_hi = TAILF;
            #pragma unroll
            for (int m = 1; m <= NBINS; m++) {
                Sh += MINVF + rhh * eh[m - 1];
                const float chm = fmaf(2.0f * TAILF, Sh, -TAILF);
                if (m == idx)     ch_lo = chm;
                if (m == idx + 1) ch_hi = chm;
            }

            const float dd0 = MINVF + softplusf(pp[2 * NBINS + idx]);
            const float dd1 = MINVF + softplusf(pp[2 * NBINS + idx + 1]);

            const float xkd = cw_hi - cw_lo;
            const float ykd = ch_hi - ch_lo;
            const float sk  = ykd / xkd;
            const float xi  = (xc - cw_lo) / xkd;
            const float xi1m = xi * (1.0f - xi);
            const float alpha = ykd * (sk * xi * xi + dd0 * xi1m);
            const float beta  = sk + (dd1 + dd0 - 2.0f * sk) * xi1m;
            const float z     = ch_lo + alpha / beta;
            const float omxi  = 1.0f - xi;
            const float dnum  = sk * sk * (dd1 * xi * xi + 2.0f * sk * xi1m + dd0 * omxi * omxi);
            const float ld = __logf(dnum) - 2.0f * __logf(beta);

            zout[(size_t)grow * D2 + j] = inside ? z : x;
            ldsum += inside ? ld : 0.0f;
        }
        __syncthreads();   // B(c) reads done; spline(c-1) done -> prm free

        if (wid < 8) {
            // refill B with chunk c+1 (single buffer; no reader until next sync)
            if (c + 1 < NCH) {
                const uint4* src = (const uint4*)g_W3B + (size_t)(c + 1) * B_TILE_U4;
                #pragma unroll
                for (int q = 0; q < 7; q++) {
                    const int i = t + q * 256;   // 256 threads x 7 = 1792
                    CP_ASYNC16(sbase + SM_B + i * 16, (const void*)(src + i));
                }
            }
            CP_COMMIT();

            // ------------------ epilogue: D + b3 -> prm ------------------
            const int g = lane >> 2, tg = lane & 3;
            const int r0 = mt * 16 + g, r1 = r0 + 8;
            const float* b3c = b3 + c * 49;
            #pragma unroll
            for (int nt4 = 0; nt4 < 4; nt4++) {
                if (tbase + nt4 >= NTILES) continue;
                const int n0 = (tbase + nt4) * 8 + 2 * tg;
                if (n0 < 49) {
                    const float bv = __ldg(b3c + n0);
                    prm[r0 * PRMSTR + n0] = d[nt4*4 + 0] + bv;
                    prm[r1 * PRMSTR + n0] = d[nt4*4 + 2] + bv;
                }
                if (n0 + 1 < 49) {
                    const float bv = __ldg(b3c + n0 + 1);
                    prm[r0 * PRMSTR + n0 + 1] = d[nt4*4 + 1] + bv;
                    prm[r1 * PRMSTR + n0 + 1] = d[nt4*4 + 3] + bv;
                }
            }
            CP_WAIT0();    // B(c+1) landed (issued before epilogue)
        }
        __syncthreads();   // prm(c) visible, B(c+1) ready
    }

    // final spline: chunk NCH-1
    if (wid >= 8) {
        const int rr   = t - 256;
        const int grow = row0 + rr;
        const int j    = NCH - 1;
        const float* pp = prm + rr * PRMSTR;

        const float x = x_next;
        const bool inside = (x >= -TAILF) && (x <= TAILF);
        const float xc = fminf(fmaxf(x, -TAILF), TAILF);

        float mw = -1e30f, mh = -1e30f;
        #pragma unroll
        for (int i = 0; i < NBINS; i++) {
            mw = fmaxf(mw, pp[i]);
            mh = fmaxf(mh, pp[NBINS + i]);
        }
        float ew[NBINS], eh[NBINS];
        float sw = 0.0f, sh = 0.0f;
        #pragma unroll
        for (int i = 0; i < NBINS; i++) {
            ew[i] = __expf(pp[i] - mw);          sw += ew[i];
            eh[i] = __expf(pp[NBINS + i] - mh);  sh += eh[i];
        }
        const float cscale = 1.0f - NBINS * MINVF;
        const float rw = cscale / sw;
        const float rhh = cscale / sh;

        float S = 0.0f;
        float cw_lo = -TAILF, cw_lo_prev = -TAILF, cw_hi = TAILF;
        int idx = 0;
        bool failed = false;
        #pragma unroll
        for (int m = 1; m <= NBINS; m++) {
            S += MINVF + rw * ew[m - 1];
            const float cwm = fmaf(2.0f * TAILF, S, -TAILF);
            const float ref = (m == NBINS) ? (cwm + EPSF) : cwm;
            if (ref <= xc) { idx = m; cw_lo_prev = cw_lo; cw_lo = cwm; }
            else if (!failed) { failed = true; cw_hi = cwm; }
        }
        if (!failed) { idx = NBINS - 1; cw_hi = cw_lo; cw_lo = cw_lo_prev; }

        float Sh = 0.0f;
        float ch_lo = -TAILF, ch_hi = TAILF;
        #pragma unroll
        for (int m = 1; m <= NBINS; m++) {
            Sh += MINVF + rhh * eh[m - 1];
            const float chm = fmaf(2.0f * TAILF, Sh, -TAILF);
            if (m == idx)     ch_lo = chm;
            if (m == idx + 1) ch_hi = chm;
        }

        const float dd0 = MINVF + softplusf(pp[2 * NBINS + idx]);
        const float dd1 = MINVF + softplusf(pp[2 * NBINS + idx + 1]);

        const float xkd = cw_hi - cw_lo;
        const float ykd = ch_hi - ch_lo;
        const float sk  = ykd / xkd;
        const float xi  = (xc - cw_lo) / xkd;
        const float xi1m = xi * (1.0f - xi);
        const float alpha = ykd * (sk * xi * xi + dd0 * xi1m);
        const float beta  = sk + (dd1 + dd0 - 2.0f * sk) * xi1m;
        const float z     = ch_lo + alpha / beta;
        const float omxi  = 1.0f - xi;
        const float dnum  = sk * sk * (dd1 * xi * xi + 2.0f * sk * xi1m + dd0 * omxi * omxi);
        const float ld = __logf(dnum) - 2.0f * __logf(beta);

        zout[(size_t)grow * D2 + j] = inside ? z : x;
        ldsum += inside ? ld : 0.0f;

        ldout[grow] = ldsum;
    }
}

extern "C" void kernel_launch(void* const* d_in, const int* in_sizes, int n_in,
                              void* d_out, int out_size)
{
    const float* x1 = (const float*)d_in[0];
    const float* x2 = (const float*)d_in[1];
    const float* W1 = (const float*)d_in[2];
    const float* b1 = (const float*)d_in[3];
    const float* W2 = (const float*)d_in[4];
    const float* b2 = (const float*)d_in[5];
    const float* W3 = (const float*)d_in[6];
    const float* b3 = (const float*)d_in[7];

    float* out = (float*)d_out;
    const int B = in_sizes[0] / D1;         // 65536
    float* zout  = out;
    float* ldout = out + (size_t)B * D2;

    prep_w3_kernel<<<(NCH * NTILES * 16 * 32 + 255) / 256, 256>>>(W3);

    cudaFuncSetAttribute(rq_fused_kernel,
                         cudaFuncAttributeMaxDynamicSharedMemorySize, SMEM_TOTAL);
    rq_fused_kernel<<<B / MROWS, THREADS, SMEM_TOTAL>>>(
        x1, x2, W1, b1, W2, b2, b3, zout, ldout);
}

// round 17
// speedup vs baseline: 1.5139x; 1.5139x over previous
#include <cuda_runtime.h>
#include <cuda_fp16.h>
#include <math.h>
#include <stdint.h>

// ---------------- problem constants ----------------
#define THREADS   320
#define MROWS     64          // batch rows per CTA (3 CTAs/SM)
#define D1        32
#define DFF       256
#define D2        32
#define NBINS     16
#define DOUT      1568        // 49*32
#define NCH       32          // one chunk per output j
#define NTILES    7           // n8 tiles per chunk (49 -> 56 padded)
#define HSTR      36          // h1T padded stride (floats)
#define PRMSTR    51          // prm stride (floats), odd -> conflict-free spline reads
#define TAILF     3.0f
#define MINVF     0.001f
#define EPSF      1e-6f

// ---------------- smem byte offsets (total 74496 per CTA -> 3 CTAs/SM) -------
#define SM_A_HI   0                         // 64x256 f16, 512B/row, XOR16 swizzle (32768 B)
#define SM_B      32768                     // B tile 7*16*32 uint2 = 28672 B
#define SM_PRM    61440                     // 64x51 f32 = 13056 B  (ends 74496)
// phase-only overlays (B+prm region unused during phases):
#define SM_H1     32768                     // 256x36 f32 = 36864 B (ends 69632)
#define SM_X1     69632                     // 32x32 f32 = 4096 B   (ends 73728)
#define SMEM_TOTAL 74496

#define B_TILE_U2 (NTILES * 16 * 32)        // 3584 uint2 per chunk
#define B_TILE_U4 (B_TILE_U2 / 2)           // 1792 uint4

typedef unsigned long long u64;

// prepped W3 hi-fragments: [c][nt][kk][lane] -> uint2{hi_b0, hi_b1}
__device__ __align__(16) uint2 g_W3B[NCH * NTILES * 16 * 32];   // 917504 B

// ---------------- helpers ----------------
__device__ __forceinline__ u64 pack2(float lo, float hi) {
    u64 r; asm("mov.b64 %0, {%1, %2};" : "=l"(r) : "f"(lo), "f"(hi)); return r;
}
__device__ __forceinline__ void unpack2(u64 v, float& lo, float& hi) {
    asm("mov.b64 {%0, %1}, %2;" : "=f"(lo), "=f"(hi) : "l"(v));
}
__device__ __forceinline__ void fma2(u64& d, u64 a, u64 b) {
    asm("fma.rn.f32x2 %0, %1, %2, %0;" : "+l"(d) : "l"(a), "l"(b));
}
__device__ __forceinline__ float softplusf(float x) {
    return fmaxf(x, 0.0f) + log1pf(__expf(-fabsf(x)));
}
__device__ __forceinline__ uint32_t smem_u32(const void* p) {
    uint32_t a;
    asm("{ .reg .u64 t; cvta.to.shared.u64 t, %1; cvt.u32.u64 %0, t; }" : "=r"(a) : "l"(p));
    return a;
}
#define CP_ASYNC16(dst, src) \
    asm volatile("cp.async.cg.shared.global [%0], [%1], 16;" :: "r"(dst), "l"(src))
#define CP_COMMIT() asm volatile("cp.async.commit_group;" ::: "memory")
#define CP_WAIT0()  asm volatile("cp.async.wait_group 0;" ::: "memory")

// ---------------- tensor-core primitives (baseline ISA, sm_80+) ----------------
__device__ __forceinline__ void ldsm_x4(uint32_t addr, uint32_t r[4]) {
    asm volatile("ldmatrix.sync.aligned.m8n8.x4.shared.b16 {%0,%1,%2,%3}, [%4];"
                 : "=r"(r[0]), "=r"(r[1]), "=r"(r[2]), "=r"(r[3]) : "r"(addr));
}
__device__ __forceinline__ void mma16816(float d[4], const uint32_t a[4],
                                         uint32_t b0, uint32_t b1) {
    asm volatile("mma.sync.aligned.m16n8k16.row.col.f32.f16.f16.f32 "
                 "{%0,%1,%2,%3}, {%4,%5,%6,%7}, {%8,%9}, {%0,%1,%2,%3};"
                 : "+f"(d[0]), "+f"(d[1]), "+f"(d[2]), "+f"(d[3])
                 : "r"(a[0]), "r"(a[1]), "r"(a[2]), "r"(a[3]), "r"(b0), "r"(b1));
}
__device__ __forceinline__ uint32_t hpack(__half a, __half b) {
    uint32_t r;
    asm("mov.b32 %0, {%1, %2};" : "=r"(r) : "h"(__half_as_ushort(a)), "h"(__half_as_ushort(b)));
    return r;
}

// =====================================================================
// spline for one (row, j): NO register arrays (exp recomputed) to stay
// under the 68-reg cap at 3 CTAs/SM without local-memory spills
// =====================================================================
__device__ __forceinline__ void spline_eval(const float* __restrict__ pp,
                                            float x, float& zres, float& ldres)
{
    const bool inside = (x >= -TAILF) && (x <= TAILF);
    const float xc = fminf(fmaxf(x, -TAILF), TAILF);

    float mw = -1e30f, mh = -1e30f;
    #pragma unroll
    for (int i = 0; i < NBINS; i++) {
        mw = fmaxf(mw, pp[i]);
        mh = fmaxf(mh, pp[NBINS + i]);
    }
    float sw = 0.0f, sh = 0.0f;
    #pragma unroll
    for (int i = 0; i < NBINS; i++) {
        sw += __expf(pp[i] - mw);
        sh += __expf(pp[NBINS + i] - mh);
    }
    const float cscale = 1.0f - NBINS * MINVF;
    const float rw = cscale / sw;
    const float rhh = cscale / sh;

    // width pass: running cumw, bin index, left/right knots (exp recomputed)
    float S = 0.0f;
    float cw_lo = -TAILF, cw_lo_prev = -TAILF, cw_hi = TAILF;
    int idx = 0;
    bool failed = false;
    #pragma unroll
    for (int m = 1; m <= NBINS; m++) {
        S += MINVF + rw * __expf(pp[m - 1] - mw);
        const float cwm = fmaf(2.0f * TAILF, S, -TAILF);
        const float ref = (m == NBINS) ? (cwm + EPSF) : cwm;
        if (ref <= xc) { idx = m; cw_lo_prev = cw_lo; cw_lo = cwm; }
        else if (!failed) { failed = true; cw_hi = cwm; }
    }
    if (!failed) { idx = NBINS - 1; cw_hi = cw_lo; cw_lo = cw_lo_prev; }

    // height pass (exp recomputed)
    float Sh = 0.0f;
    float ch_lo = -TAILF, ch_hi = TAILF;
    #pragma unroll
    for (int m = 1; m <= NBINS; m++) {
        Sh += MINVF + rhh * __expf(pp[NBINS + m - 1] - mh);
        const float chm = fmaf(2.0f * TAILF, Sh, -TAILF);
        if (m == idx)     ch_lo = chm;
        if (m == idx + 1) ch_hi = chm;
    }

    const float dd0 = MINVF + softplusf(pp[2 * NBINS + idx]);
    const float dd1 = MINVF + softplusf(pp[2 * NBINS + idx + 1]);

    const float xkd = cw_hi - cw_lo;
    const float ykd = ch_hi - ch_lo;
    const float sk  = ykd / xkd;
    const float xi  = (xc - cw_lo) / xkd;
    const float xi1m = xi * (1.0f - xi);
    const float alpha = ykd * (sk * xi * xi + dd0 * xi1m);
    const float beta  = sk + (dd1 + dd0 - 2.0f * sk) * xi1m;
    const float z     = ch_lo + alpha / beta;
    const float omxi  = 1.0f - xi;
    const float dnum  = sk * sk * (dd1 * xi * xi + 2.0f * sk * xi1m + dd0 * omxi * omxi);
    const float ld = __logf(dnum) - 2.0f * __logf(beta);

    zres  = inside ? z : x;
    ldres = inside ? ld : 0.0f;
}

// =====================================================================
// prep kernel: W3 [256 x 1568] -> per-lane hi B fragments, 7 tiles/chunk
// =====================================================================
__global__ void prep_w3_kernel(const float* __restrict__ W3) {
    int id = blockIdx.x * blockDim.x + threadIdx.x;
    if (id >= NCH * NTILES * 16 * 32) return;
    const int lane = id & 31;
    const int kk   = (id >> 5) & 15;
    const int rest = id >> 9;
    const int nt   = rest % NTILES;
    const int c    = rest / NTILES;
    const int g = lane >> 2, tg = lane & 3;
    const int n = nt * 8 + g;                 // 0..55
    float w00 = 0.f, w01 = 0.f, w10 = 0.f, w11 = 0.f;
    if (n < 49) {
        const size_t pi = (size_t)c * 49 + n;
        const int k0 = kk * 16 + 2 * tg;
        w00 = W3[(size_t)(k0    ) * DOUT + pi];
        w01 = W3[(size_t)(k0 + 1) * DOUT + pi];
        w10 = W3[(size_t)(k0 + 8) * DOUT + pi];
        w11 = W3[(size_t)(k0 + 9) * DOUT + pi];
    }
    uint2 v;
    v.x = hpack(__float2half_rn(w00), __float2half_rn(w01));
    v.y = hpack(__float2half_rn(w10), __float2half_rn(w11));
    g_W3B[((c * NTILES + nt) * 16 + kk) * 32 + lane] = v;
}

// =====================================================================
// main fused kernel: 3 CTAs/SM, single f16 product (Ah*Bh)
//   warps 0-7: MMA (mt4 x nh2, M16 x N32/24); warps 8-9: spline(c-1)
// =====================================================================
__global__ __launch_bounds__(THREADS, 3)
void rq_fused_kernel(const float* __restrict__ x1,
                     const float* __restrict__ x2,
                     const float* __restrict__ W1,
                     const float* __restrict__ b1,
                     const float* __restrict__ W2,
                     const float* __restrict__ b2,
                     const float* __restrict__ b3,
                     float* __restrict__ zout,
                     float* __restrict__ ldout)
{
    extern __shared__ char smem[];
    const uint32_t sbase = smem_u32(smem);
    float* x1s = (float*)(smem + SM_X1);
    float* h1T = (float*)(smem + SM_H1);
    float* prm = (float*)(smem + SM_PRM);
    const uint2* Bsm = (const uint2*)(smem + SM_B);

    const int t    = threadIdx.x;
    const int wid  = t >> 5;
    const int lane = t & 31;
    const int row0 = blockIdx.x * MROWS;

    // ---------------- phases 1+2 (SIMT fp32x2, threads 0-255): 2 sub-blocks of 32 rows
    for (int sub = 0; sub < 2; sub++) {
        if (t < 256)
            for (int i = t; i < 32 * D1; i += 256)
                x1s[i] = x1[(size_t)(row0 + sub * 32) * D1 + i];
        __syncthreads();

        if (t < 256) {
            const int col = t;
            // phase 1: h1 = relu(x1 @ W1 + b1), 32 rows
            float w1r[D1];
            #pragma unroll
            for (int k = 0; k < D1; k++) w1r[k] = W1[k * DFF + col];
            const float bb = b1[col];
            #pragma unroll
            for (int rr = 0; rr < 32; rr++) {
                float acc = bb;
                #pragma unroll
                for (int k = 0; k < D1; k++)
                    acc = fmaf(x1s[rr * D1 + k], w1r[k], acc);
                h1T[col * HSTR + rr] = fmaxf(acc, 0.0f);
            }
        }
        __syncthreads();

        if (t < 256) {
            const int col = t;
            // phase 2: h2 = relu(h1 @ W2 + b2) -> A_hi f16 (XOR16-swizzled)
            u64 acc2[16];
            const float bb = b2[col];
            #pragma unroll
            for (int q = 0; q < 16; q++) acc2[q] = pack2(bb, bb);
            #pragma unroll 2
            for (int k = 0; k < DFF; k++) {
                const float w = __ldg(W2 + k * DFF + col);
                const u64 w2 = pack2(w, w);
                const ulonglong2* h4 = reinterpret_cast<const ulonglong2*>(h1T + k * HSTR);
                #pragma unroll
                for (int q = 0; q < 8; q++) {
                    ulonglong2 a = h4[q];
                    fma2(acc2[2*q + 0], a.x, w2);
                    fma2(acc2[2*q + 1], a.y, w2);
                }
            }
            #pragma unroll
            for (int q = 0; q < 16; q++) {
                float lo, hi;
                unpack2(acc2[q], lo, hi);
                #pragma unroll
                for (int e = 0; e < 2; e++) {
                    const float v = fmaxf(e ? hi : lo, 0.0f);
                    const int r = sub * 32 + 2 * q + e;
                    const uint32_t ao = (uint32_t)(r * 512 + col * 2) ^ ((uint32_t)(r & 7) << 4);
                    *(__half*)(smem + SM_A_HI + ao) = __float2half_rn(v);
                }
            }
        }
        __syncthreads();
    }

    // preload B chunk 0 (28672 B = 1792 uint4)
    {
        const uint4* src = (const uint4*)g_W3B;
        for (int i = t; i < B_TILE_U4; i += THREADS)
            CP_ASYNC16(sbase + SM_B + i * 16, (const void*)(src + i));
        CP_COMMIT(); CP_WAIT0();
    }
    __syncthreads();

    // =====================================================================
    // chunk pipeline (single B buffer, refilled between syncs)
    // =====================================================================
    float ldsum = 0.0f;

    const int mt = wid & 3;        // 16-row M-tile (0-3)
    const int nh = wid >> 2;       // 0: tiles 0-3, 1: tiles 4-6
    const int tbase = nh * 4;
    const uint32_t arow  = (uint32_t)(mt * 16 + (lane & 15));
    const uint32_t abase = arow * 512 + ((lane >> 4) << 4);
    const uint32_t aswz  = (arow & 7) << 4;

    // spline-side x2 prefetch (one chunk ahead)
    float x_next = 0.0f;
    if (wid >= 8) {
        const int rr = t - 256;                              // 0..63
        x_next = __ldg(x2 + (size_t)(row0 + rr) * D2 + 0);   // j=0
    }

    #pragma unroll 1
    for (int c = 0; c < NCH; c++) {
        float d[16];
        if (wid < 8) {
            // ------------------ MMA mainloop (hi*hi only), double-buffered frags -----
            #pragma unroll
            for (int i = 0; i < 16; i++) d[i] = 0.0f;

            uint32_t ah[2][4];
            uint2 bb[2][4];
            {   // preload kk = 0
                const uint32_t o = abase ^ aswz;
                ldsm_x4(sbase + SM_A_HI + o, ah[0]);
                #pragma unroll
                for (int nt4 = 0; nt4 < 4; nt4++)
                    if (tbase + nt4 < NTILES)
                        bb[0][nt4] = Bsm[((tbase + nt4) * 16 + 0) * 32 + lane];
            }
            #pragma unroll
            for (int kk = 0; kk < 16; kk++) {
                const int cur = kk & 1, nxt = cur ^ 1;
                if (kk < 15) {
                    const uint32_t o = (abase + (kk + 1) * 32) ^ aswz;
                    ldsm_x4(sbase + SM_A_HI + o, ah[nxt]);
                    #pragma unroll
                    for (int nt4 = 0; nt4 < 4; nt4++)
                        if (tbase + nt4 < NTILES)
                            bb[nxt][nt4] = Bsm[((tbase + nt4) * 16 + (kk + 1)) * 32 + lane];
                }
                #pragma unroll
                for (int nt4 = 0; nt4 < 4; nt4++)
                    if (tbase + nt4 < NTILES)
                        mma16816(d + nt4 * 4, ah[cur], bb[cur][nt4].x, bb[cur][nt4].y);
            }
        } else if (c > 0) {
            // ------------------ spline warps: chunk c-1, row rr = t-256 --------------
            const int rr   = t - 256;          // 0..63
            const int grow = row0 + rr;
            const float x = x_next;
            if (c < NCH) x_next = __ldg(x2 + (size_t)grow * D2 + c);

            float z, ld;
            spline_eval(prm + rr * PRMSTR, x, z, ld);
            zout[(size_t)grow * D2 + (c - 1)] = z;
            ldsum += ld;
        }
        __syncthreads();   // B(c) reads done; spline(c-1) done -> prm free

        if (wid < 8) {
            // refill B with chunk c+1 (single buffer; no reader until next sync)
            if (c + 1 < NCH) {
                const uint4* src = (const uint4*)g_W3B + (size_t)(c + 1) * B_TILE_U4;
                #pragma unroll
                for (int q = 0; q < 7; q++) {
                    const int i = t + q * 256;   // 256 threads x 7 = 1792
                    CP_ASYNC16(sbase + SM_B + i * 16, (const void*)(src + i));
                }
            }
            CP_COMMIT();

            // ------------------ epilogue: D + b3 -> prm ------------------
            const int g = lane >> 2, tg = lane & 3;
            const int r0 = mt * 16 + g, r1 = r0 + 8;
            const float* b3c = b3 + c * 49;
            #pragma unroll
            for (int nt4 = 0; nt4 < 4; nt4++) {
                if (tbase + nt4 >= NTILES) continue;
                const int n0 = (tbase + nt4) * 8 + 2 * tg;
                if (n0 < 49) {
                    const float bv = __ldg(b3c + n0);
                    prm[r0 * PRMSTR + n0] = d[nt4*4 + 0] + bv;
                    prm[r1 * PRMSTR + n0] = d[nt4*4 + 2] + bv;
                }
                if (n0 + 1 < 49) {
                    const float bv = __ldg(b3c + n0 + 1);
                    prm[r0 * PRMSTR + n0 + 1] = d[nt4*4 + 1] + bv;
                    prm[r1 * PRMSTR + n0 + 1] = d[nt4*4 + 3] + bv;
                }
            }
            CP_WAIT0();    // B(c+1) landed (issued before epilogue)
        }
        __syncthreads();   // prm(c) visible, B(c+1) ready
    }

    // final spline: chunk NCH-1
    if (wid >= 8) {
        const int rr   = t - 256;
        const int grow = row0 + rr;
        float z, ld;
        spline_eval(prm + rr * PRMSTR, x_next, z, ld);
        zout[(size_t)grow * D2 + (NCH - 1)] = z;
        ldsum += ld;
        ldout[grow] = ldsum;
    }
}

extern "C" void kernel_launch(void* const* d_in, const int* in_sizes, int n_in,
                              void* d_out, int out_size)
{
    const float* x1 = (const float*)d_in[0];
    const float* x2 = (const float*)d_in[1];
    const float* W1 = (const float*)d_in[2];
    const float* b1 = (const float*)d_in[3];
    const float* W2 = (const float*)d_in[4];
    const float* b2 = (const float*)d_in[5];
    const float* W3 = (const float*)d_in[6];
    const float* b3 = (const float*)d_in[7];

    float* out = (float*)d_out;
    const int B = in_sizes[0] / D1;         // 65536
    float* zout  = out;
    float* ldout = out + (size_t)B * D2;

    prep_w3_kernel<<<(NCH * NTILES * 16 * 32 + 255) / 256, 256>>>(W3);

    cudaFuncSetAttribute(rq_fused_kernel,
                         cudaFuncAttributeMaxDynamicSharedMemorySize, SMEM_TOTAL);
    rq_fused_kernel<<<B / MROWS, THREADS, SMEM_TOTAL>>>(
        x1, x2, W1, b1, W2, b2, b3, zout, ldout);
}